// round 15
// baseline (speedup 1.0000x reference)
#include <cuda_runtime.h>
#include <cstdint>

#define T_SEQ 1024
#define CDIM  1024
#define C3    3072
#define NH    16
#define HD    64
#define BATCH 8
#define THRESH 0.001f

#define GS  20    // GEMM smem row stride (16 + 4 pad; %8==4 -> ldmatrix conflict-free)
#define KS  68    // attention K/Q smem stride
#define VS  72    // attention V smem stride
#define OST 36    // o-reduction smem stride

// Scratch (device globals: allocation-free per harness rules)
__device__ float g_qkv[(size_t)BATCH * T_SEQ * C3];   // 96 MB
__device__ float g_y[(size_t)BATCH * T_SEQ * CDIM];   // 32 MB
__device__ float g_xr[(size_t)BATCH * T_SEQ * CDIM];  // 32 MB  (tf32-rounded x)
__device__ float g_wat[(size_t)C3 * CDIM];            // 12 MB  (w_attn^T, rounded)
__device__ float g_wpt[(size_t)CDIM * CDIM];          // 4 MB   (w_proj^T, rounded)

// ---------------------------------------------------------------------------
__device__ __forceinline__ float f2tf(float x) {
    uint32_t u;
    asm("cvt.rna.tf32.f32 %0, %1;" : "=r"(u) : "f"(x));
    return __uint_as_float(u);
}

__device__ __forceinline__ void mma_tf32(float* d, const float* a, const float* b) {
    asm volatile(
        "mma.sync.aligned.m16n8k8.row.col.f32.tf32.tf32.f32 "
        "{%0,%1,%2,%3}, {%4,%5,%6,%7}, {%8,%9}, {%0,%1,%2,%3};"
        : "+f"(d[0]), "+f"(d[1]), "+f"(d[2]), "+f"(d[3])
        : "r"(__float_as_uint(a[0])), "r"(__float_as_uint(a[1])),
          "r"(__float_as_uint(a[2])), "r"(__float_as_uint(a[3])),
          "r"(__float_as_uint(b[0])), "r"(__float_as_uint(b[1])));
}

__device__ __forceinline__ void mma_tf32u(float* d, const uint32_t* a, const uint32_t* b) {
    asm volatile(
        "mma.sync.aligned.m16n8k8.row.col.f32.tf32.tf32.f32 "
        "{%0,%1,%2,%3}, {%4,%5,%6,%7}, {%8,%9}, {%0,%1,%2,%3};"
        : "+f"(d[0]), "+f"(d[1]), "+f"(d[2]), "+f"(d[3])
        : "r"(a[0]), "r"(a[1]), "r"(a[2]), "r"(a[3]), "r"(b[0]), "r"(b[1]));
}

__device__ __forceinline__ void ldsm4(uint32_t* r, uint32_t addr) {
    asm volatile("ldmatrix.sync.aligned.m8n8.x4.shared.b16 {%0,%1,%2,%3}, [%4];"
                 : "=r"(r[0]), "=r"(r[1]), "=r"(r[2]), "=r"(r[3]) : "r"(addr));
}

__device__ __forceinline__ void cp16(uint32_t dst, const void* src) {
    asm volatile("cp.async.cg.shared.global [%0], [%1], 16;" :: "r"(dst), "l"(src));
}

// ---------------------------------------------------------------------------
// prepass: tf32-round a float array (float4 vectorized)
// ---------------------------------------------------------------------------
__global__ void round_tf32(const float4* __restrict__ in, float4* __restrict__ out,
                           int n4)
{
    int i = blockIdx.x * blockDim.x + threadIdx.x;
    if (i < n4) {
        float4 v = in[i];
        out[i] = make_float4(f2tf(v.x), f2tf(v.y), f2tf(v.z), f2tf(v.w));
    }
}

// prepass: w[K][N] -> wt[N][K], tf32-rounded. block (32,8), grid (N/32, K/32)
__global__ void transpose_round(const float* __restrict__ in, float* __restrict__ out,
                                int K, int N)
{
    __shared__ float tile[32][33];
    int tx = threadIdx.x, ty = threadIdx.y;
    int x = blockIdx.x * 32 + tx;            // n
    int y = blockIdx.y * 32 + ty;            // k
    #pragma unroll
    for (int j = 0; j < 32; j += 8)
        tile[ty + j][tx] = in[(size_t)(y + j) * N + x];
    __syncthreads();
    int xo = blockIdx.y * 32 + tx;           // k
    int yo = blockIdx.x * 32 + ty;           // n
    #pragma unroll
    for (int j = 0; j < 32; j += 8)
        out[(size_t)(yo + j) * K + xo] = f2tf(tile[tx][ty + j]);
}

// ---------------------------------------------------------------------------
// tf32 tensor-core GEMM + bias: C[M,N] = A[M,K] @ Bt[N,K]^T + bias[N]
// Inputs pre-rounded to tf32. cp.async double-buffered loads, ldmatrix frags.
// 128 threads / 4 warps, block 128x128, warp tile 64x64, BK=16.
// ---------------------------------------------------------------------------
__global__ __launch_bounds__(128) void gemm_tf32(
    const float* __restrict__ A, const float* __restrict__ Bt,
    const float* __restrict__ bias, float* __restrict__ C,
    int M, int N, int K, int roundOut)
{
    __shared__ float As[2][128 * GS];
    __shared__ float Bs[2][128 * GS];

    int tid  = threadIdx.x;
    int lane = tid & 31, w = tid >> 5;
    int g = lane >> 2, t = lane & 3;
    int wm = w >> 1, wn = w & 1;
    int bx = blockIdx.x, by = blockIdx.y;

    const float* A0 = A  + (size_t)(by * 128 + tid) * K;
    const float* B0 = Bt + (size_t)(bx * 128 + tid) * K;

    uint32_t sA0 = (uint32_t)__cvta_generic_to_shared(&As[0][0]);
    uint32_t sB0 = (uint32_t)__cvta_generic_to_shared(&Bs[0][0]);
    uint32_t sA = sA0 + tid * (GS * 4);
    uint32_t sB = sB0 + tid * (GS * 4);

    // ldmatrix per-lane fragment addresses (row*GS*4 + (lane>=16 ? 16 : 0))
    uint32_t aF[4], bF[4];
    #pragma unroll
    for (int mt = 0; mt < 4; mt++)
        aF[mt] = sA0 + (uint32_t)(wm * 64 + mt * 16 + (lane & 15)) * (GS * 4)
               + ((lane >> 4) << 4);
    #pragma unroll
    for (int p2 = 0; p2 < 4; p2++)
        bF[p2] = sB0 + (uint32_t)(wn * 64 + p2 * 16 + (lane & 15)) * (GS * 4)
               + ((lane >> 4) << 4);

    float acc[4][8][4];
    #pragma unroll
    for (int mt = 0; mt < 4; mt++)
        #pragma unroll
        for (int nt = 0; nt < 8; nt++)
            #pragma unroll
            for (int i = 0; i < 4; i++) acc[mt][nt][i] = 0.f;

    const uint32_t BUFB = 128 * GS * 4;   // bytes per buffer

    // prologue: fill buffer 0
    #pragma unroll
    for (int i = 0; i < 4; i++) cp16(sA + i * 16, A0 + i * 4);
    #pragma unroll
    for (int i = 0; i < 4; i++) cp16(sB + i * 16, B0 + i * 4);
    asm volatile("cp.async.commit_group;");

    for (int k0 = 0; k0 < K; k0 += 16) {
        uint32_t pb = ((k0 >> 4) & 1) * BUFB;
        asm volatile("cp.async.wait_group 0;" ::: "memory");
        __syncthreads();

        if (k0 + 16 < K) {
            uint32_t pn = pb ^ BUFB;
            #pragma unroll
            for (int i = 0; i < 4; i++) cp16(sA + pn + i * 16, A0 + k0 + 16 + i * 4);
            #pragma unroll
            for (int i = 0; i < 4; i++) cp16(sB + pn + i * 16, B0 + k0 + 16 + i * 4);
            asm volatile("cp.async.commit_group;");
        }

        uint32_t af[2][4][4], bf[2][8][2];
        #pragma unroll
        for (int hh = 0; hh < 2; hh++) {
            uint32_t ko = pb + hh * 32;    // kk=8 -> +32 bytes
            #pragma unroll
            for (int mt = 0; mt < 4; mt++) ldsm4(af[hh][mt], aF[mt] + ko);
            #pragma unroll
            for (int p2 = 0; p2 < 4; p2++) {
                uint32_t r[4];
                ldsm4(r, bF[p2] + ko);
                bf[hh][2 * p2][0] = r[0]; bf[hh][2 * p2 + 1][0] = r[1];
                bf[hh][2 * p2][1] = r[2]; bf[hh][2 * p2 + 1][1] = r[3];
            }
        }
        #pragma unroll
        for (int hh = 0; hh < 2; hh++)
            #pragma unroll
            for (int mt = 0; mt < 4; mt++)
                #pragma unroll
                for (int nt = 0; nt < 8; nt++)
                    mma_tf32u(acc[mt][nt], af[hh][mt], bf[hh][nt]);
    }

    #pragma unroll
    for (int mt = 0; mt < 4; mt++) {
        #pragma unroll
        for (int nt = 0; nt < 8; nt++) {
            int r0 = by * 128 + wm * 64 + mt * 16 + g;
            int c0 = bx * 128 + wn * 64 + nt * 8 + 2 * t;
            float b0 = bias[c0], b1 = bias[c0 + 1];
            float v0 = acc[mt][nt][0] + b0, v1 = acc[mt][nt][1] + b1;
            float v2 = acc[mt][nt][2] + b0, v3 = acc[mt][nt][3] + b1;
            if (roundOut) {
                v0 = f2tf(v0); v1 = f2tf(v1); v2 = f2tf(v2); v3 = f2tf(v3);
            }
            *(float2*)(C + (size_t)r0 * N + c0)       = make_float2(v0, v1);
            *(float2*)(C + (size_t)(r0 + 8) * N + c0) = make_float2(v2, v3);
        }
    }
}

// ---------------------------------------------------------------------------
// Two-pass tensor-core flash attention, post-softmax threshold, no max
// subtraction. qkv arrives pre-rounded to tf32 (GEMM epilogue), so K/V/Q
// commits are plain copies. y is tf32-rounded at write for the proj GEMM.
// ---------------------------------------------------------------------------
__global__ __launch_bounds__(256) void attn_tf32(
    const float* __restrict__ qkv, float* __restrict__ y)
{
    extern __shared__ float sm[];
    float* K0   = sm;                    // [64][KS] (also Q staging / osum)
    float* K1   = K0 + 64 * KS;
    float* V0   = K1 + 64 * KS;          // [64][VS]
    float* V1   = V0 + 64 * VS;
    float* red  = V1 + 64 * VS;          // [128]
    float* zinv = red + 128;             // [64]
    float* osum = K0;                    // [4][32][OST] overlay after pass 2

    int tid = threadIdx.x;
    int w = tid >> 5, lane = tid & 31;
    int g = lane >> 2, t = lane & 3;
    int wm = w >> 1, wn = w & 1;
    int qt = blockIdx.x, h = blockIdx.y, b = blockIdx.z;

    const float* Qg = qkv + ((size_t)(b * T_SEQ + qt * 64)) * C3 + h * HD;
    const float* Kg = qkv + (size_t)b * T_SEQ * C3 + CDIM + h * HD;
    const float* Vg = Kg + CDIM;

    int lr = tid >> 2;
    int lc = (tid & 3) * 4;

    // stage Q (scaled by exact 1/8; input already tf32) and hoist fragments
    #pragma unroll
    for (int cc = 0; cc < 4; cc++) {
        float4 v = *(const float4*)(Qg + (size_t)lr * C3 + lc + cc * 16);
        *(float4*)&K0[lr * KS + lc + cc * 16] =
            make_float4(v.x * 0.125f, v.y * 0.125f, v.z * 0.125f, v.w * 0.125f);
    }
    __syncthreads();

    int r1 = wm * 16 + g, r2 = r1 + 8;

    float qa[8][4];
    #pragma unroll
    for (int kc = 0; kc < 8; kc++) {
        qa[kc][0] = K0[r1 * KS + kc * 8 + t];
        qa[kc][1] = K0[r2 * KS + kc * 8 + t];
        qa[kc][2] = K0[r1 * KS + kc * 8 + t + 4];
        qa[kc][3] = K0[r2 * KS + kc * 8 + t + 4];
    }
    __syncthreads();

    // ================= Pass 1: Z only, registers =================
    float z1 = 0.f, z2 = 0.f;
    float4 rk[4];
    #pragma unroll
    for (int cc = 0; cc < 4; cc++)
        rk[cc] = *(const float4*)(Kg + (size_t)lr * C3 + lc + cc * 16);

    for (int kt = 0; kt < 16; kt++) {
        float* Kb = (kt & 1) ? K1 : K0;
        #pragma unroll
        for (int cc = 0; cc < 4; cc++)
            *(float4*)&Kb[lr * KS + lc + cc * 16] = rk[cc];
        __syncthreads();

        if (kt < 15) {
            #pragma unroll
            for (int cc = 0; cc < 4; cc++)
                rk[cc] = *(const float4*)(Kg + (size_t)((kt + 1) * 64 + lr) * C3 + lc + cc * 16);
        }

        float s[4][4];
        #pragma unroll
        for (int nt = 0; nt < 4; nt++)
            #pragma unroll
            for (int i = 0; i < 4; i++) s[nt][i] = 0.f;

        #pragma unroll
        for (int kc = 0; kc < 8; kc++) {
            float bf[4][2];
            #pragma unroll
            for (int nt = 0; nt < 4; nt++) {
                int kr = wn * 32 + nt * 8 + g;
                bf[nt][0] = Kb[kr * KS + kc * 8 + t];
                bf[nt][1] = Kb[kr * KS + kc * 8 + t + 4];
            }
            #pragma unroll
            for (int nt = 0; nt < 4; nt++) mma_tf32(s[nt], qa[kc], bf[nt]);
        }

        #pragma unroll
        for (int nt = 0; nt < 4; nt++) {
            z1 += __expf(s[nt][0]) + __expf(s[nt][1]);
            z2 += __expf(s[nt][2]) + __expf(s[nt][3]);
        }
    }

    z1 += __shfl_xor_sync(0xffffffffu, z1, 1);
    z1 += __shfl_xor_sync(0xffffffffu, z1, 2);
    z2 += __shfl_xor_sync(0xffffffffu, z2, 1);
    z2 += __shfl_xor_sync(0xffffffffu, z2, 2);
    if (t == 0) { red[wn * 64 + r1] = z1; red[wn * 64 + r2] = z2; }
    __syncthreads();
    if (tid < 64) zinv[tid] = 1.f / (red[tid] + red[64 + tid]);
    __syncthreads();
    float li1 = zinv[r1], li2 = zinv[r2];

    float o[8][4];
    #pragma unroll
    for (int nt = 0; nt < 8; nt++)
        #pragma unroll
        for (int i = 0; i < 4; i++) o[nt][i] = 0.f;

    // ================= Pass 2: threshold + PV (shfl fragments) =============
    float4 rv[4];
    #pragma unroll
    for (int cc = 0; cc < 4; cc++) {
        rk[cc] = *(const float4*)(Kg + (size_t)lr * C3 + lc + cc * 16);
        rv[cc] = *(const float4*)(Vg + (size_t)lr * C3 + lc + cc * 16);
    }

    int srcA = (lane & 28) | (t >> 1);
    int srcB = srcA + 2;

    for (int kt = 0; kt < 16; kt++) {
        float* Kb = (kt & 1) ? K1 : K0;
        float* Vb = (kt & 1) ? V1 : V0;
        #pragma unroll
        for (int cc = 0; cc < 4; cc++) {
            *(float4*)&Kb[lr * KS + lc + cc * 16] = rk[cc];
            *(float4*)&Vb[lr * VS + lc + cc * 16] = rv[cc];
        }
        __syncthreads();

        if (kt < 15) {
            #pragma unroll
            for (int cc = 0; cc < 4; cc++) {
                size_t rg = (size_t)((kt + 1) * 64 + lr) * C3 + lc + cc * 16;
                rk[cc] = *(const float4*)(Kg + rg);
                rv[cc] = *(const float4*)(Vg + rg);
            }
        }

        float s[4][4];
        #pragma unroll
        for (int nt = 0; nt < 4; nt++)
            #pragma unroll
            for (int i = 0; i < 4; i++) s[nt][i] = 0.f;

        #pragma unroll
        for (int kc = 0; kc < 8; kc++) {
            float bf[4][2];
            #pragma unroll
            for (int nt = 0; nt < 4; nt++) {
                int kr = wn * 32 + nt * 8 + g;
                bf[nt][0] = Kb[kr * KS + kc * 8 + t];
                bf[nt][1] = Kb[kr * KS + kc * 8 + t + 4];
            }
            #pragma unroll
            for (int nt = 0; nt < 4; nt++) mma_tf32(s[nt], qa[kc], bf[nt]);
        }

        #pragma unroll
        for (int nt = 0; nt < 4; nt++) {
            s[nt][0] = f2tf(fmaxf(__expf(s[nt][0]) * li1 - THRESH, 0.f));
            s[nt][1] = f2tf(fmaxf(__expf(s[nt][1]) * li1 - THRESH, 0.f));
            s[nt][2] = f2tf(fmaxf(__expf(s[nt][2]) * li2 - THRESH, 0.f));
            s[nt][3] = f2tf(fmaxf(__expf(s[nt][3]) * li2 - THRESH, 0.f));
        }

        bool odd = (t & 1);
        #pragma unroll
        for (int kc = 0; kc < 4; kc++) {
            float e0 = __shfl_sync(0xffffffffu, s[kc][0], srcA);
            float e1 = __shfl_sync(0xffffffffu, s[kc][1], srcA);
            float e2 = __shfl_sync(0xffffffffu, s[kc][2], srcA);
            float e3 = __shfl_sync(0xffffffffu, s[kc][3], srcA);
            float f0 = __shfl_sync(0xffffffffu, s[kc][0], srcB);
            float f1 = __shfl_sync(0xffffffffu, s[kc][1], srcB);
            float f2 = __shfl_sync(0xffffffffu, s[kc][2], srcB);
            float f3 = __shfl_sync(0xffffffffu, s[kc][3], srcB);
            float pa[4];
            pa[0] = odd ? e1 : e0;
            pa[1] = odd ? e3 : e2;
            pa[2] = odd ? f1 : f0;
            pa[3] = odd ? f3 : f2;

            int krow = wn * 32 + kc * 8;
            #pragma unroll
            for (int nt = 0; nt < 8; nt++) {
                int dc = nt * 8 + g;
                float bf[2];
                bf[0] = Vb[(krow + t) * VS + dc];
                bf[1] = Vb[(krow + t + 4) * VS + dc];
                mma_tf32(o[nt], pa, bf);
            }
        }
    }

    // reduce O across the two key-halves, write y tf32-rounded (proj A input)
    __syncthreads();
    if (wn == 1) {
        float* dst = osum + (wm * 32 + lane) * OST;
        #pragma unroll
        for (int nt = 0; nt < 8; nt++)
            *(float4*)(dst + nt * 4) = *(float4*)o[nt];
    }
    __syncthreads();
    if (wn == 0) {
        const float* src = osum + (wm * 32 + lane) * OST;
        size_t rowg = (size_t)b * T_SEQ + qt * 64;
        #pragma unroll
        for (int nt = 0; nt < 8; nt++) {
            float4 p = *(const float4*)(src + nt * 4);
            int c0 = h * HD + nt * 8 + 2 * t;
            *(float2*)(y + (rowg + r1) * CDIM + c0) =
                make_float2(f2tf(o[nt][0] + p.x), f2tf(o[nt][1] + p.y));
            *(float2*)(y + (rowg + r2) * CDIM + c0) =
                make_float2(f2tf(o[nt][2] + p.z), f2tf(o[nt][3] + p.w));
        }
    }
}

// ---------------------------------------------------------------------------

extern "C" void kernel_launch(void* const* d_in, const int* in_sizes, int n_in,
                              void* d_out, int out_size)
{
    const float* x      = (const float*)d_in[0];
    const float* w_attn = (const float*)d_in[1];
    const float* b_attn = (const float*)d_in[2];
    const float* w_proj = (const float*)d_in[3];
    const float* b_proj = (const float*)d_in[4];
    float* out = (float*)d_out;

    float *qkv, *yb, *xr, *wat, *wpt;
    cudaGetSymbolAddress((void**)&qkv, g_qkv);
    cudaGetSymbolAddress((void**)&yb,  g_y);
    cudaGetSymbolAddress((void**)&xr,  g_xr);
    cudaGetSymbolAddress((void**)&wat, g_wat);
    cudaGetSymbolAddress((void**)&wpt, g_wpt);

    const int SMEM_ATTN =
        (2 * 64 * KS + 2 * 64 * VS + 128 + 64) * (int)sizeof(float);
    cudaFuncSetAttribute(attn_tf32,
                         cudaFuncAttributeMaxDynamicSharedMemorySize, SMEM_ATTN);

    // 0) prepasses: round x; transpose+round weights to [N][K]
    int n4 = (BATCH * T_SEQ * CDIM) / 4;
    round_tf32<<<(n4 + 255) / 256, 256>>>((const float4*)x, (float4*)xr, n4);
    transpose_round<<<dim3(C3 / 32, CDIM / 32), dim3(32, 8)>>>(w_attn, wat, CDIM, C3);
    transpose_round<<<dim3(CDIM / 32, CDIM / 32), dim3(32, 8)>>>(w_proj, wpt, CDIM, CDIM);

    // 1) QKV = xr @ wat^T + b_attn, output rounded to tf32
    gemm_tf32<<<dim3(C3 / 128, (BATCH * T_SEQ) / 128), 128>>>(
        xr, wat, b_attn, qkv, BATCH * T_SEQ, C3, CDIM, 1);

    // 2) attention with post-softmax threshold -> y (tf32-rounded)
    attn_tf32<<<dim3(T_SEQ / 64, NH, BATCH), 256, SMEM_ATTN>>>(qkv, yb);

    // 3) out = y @ wpt^T + b_proj (fp32 output)
    gemm_tf32<<<dim3(CDIM / 128, (BATCH * T_SEQ) / 128), 128>>>(
        yb, wpt, b_proj, out, BATCH * T_SEQ, CDIM, CDIM, 0);
}

// round 16
// speedup vs baseline: 1.3177x; 1.3177x over previous
#include <cuda_runtime.h>
#include <cstdint>

#define T_SEQ 1024
#define CDIM  1024
#define C3    3072
#define NH    16
#define HD    64
#define BATCH 8
#define THRESH 0.001f

#define AST 20    // GEMM As stride (row-major M x K, 16+4 pad)
#define BST 136   // GEMM Bs stride (K x N, 136%32==8)
#define KS  68    // attention K/Q smem stride
#define VS  72    // attention V smem stride
#define OST 36    // o-reduction smem stride

// Scratch (device globals: allocation-free per harness rules)
__device__ float g_qkv[(size_t)BATCH * T_SEQ * C3];   // 96 MB
__device__ float g_y[(size_t)BATCH * T_SEQ * CDIM];   // 32 MB
__device__ float g_xr[(size_t)BATCH * T_SEQ * CDIM];  // 32 MB (tf32-rounded x)
__device__ float g_war[(size_t)CDIM * C3];            // 12 MB (w_attn rounded, [K][N])
__device__ float g_wpr[(size_t)CDIM * CDIM];          // 4 MB  (w_proj rounded, [K][N])

// ---------------------------------------------------------------------------
__device__ __forceinline__ float f2tf(float x) {
    uint32_t u;
    asm("cvt.rna.tf32.f32 %0, %1;" : "=r"(u) : "f"(x));
    return __uint_as_float(u);
}

__device__ __forceinline__ void mma_tf32(float* d, const float* a, const float* b) {
    asm volatile(
        "mma.sync.aligned.m16n8k8.row.col.f32.tf32.tf32.f32 "
        "{%0,%1,%2,%3}, {%4,%5,%6,%7}, {%8,%9}, {%0,%1,%2,%3};"
        : "+f"(d[0]), "+f"(d[1]), "+f"(d[2]), "+f"(d[3])
        : "r"(__float_as_uint(a[0])), "r"(__float_as_uint(a[1])),
          "r"(__float_as_uint(a[2])), "r"(__float_as_uint(a[3])),
          "r"(__float_as_uint(b[0])), "r"(__float_as_uint(b[1])));
}

__device__ __forceinline__ void cp16(uint32_t dst, const void* src) {
    asm volatile("cp.async.cg.shared.global [%0], [%1], 16;" :: "r"(dst), "l"(src));
}

// ---------------------------------------------------------------------------
// prepass: tf32-round a float array (float4 vectorized)
// ---------------------------------------------------------------------------
__global__ void round_tf32(const float4* __restrict__ in, float4* __restrict__ out,
                           int n4)
{
    int i = blockIdx.x * blockDim.x + threadIdx.x;
    if (i < n4) {
        float4 v = in[i];
        out[i] = make_float4(f2tf(v.x), f2tf(v.y), f2tf(v.z), f2tf(v.w));
    }
}

// ---------------------------------------------------------------------------
// tf32 tensor-core GEMM + bias: C[M,N] = A[M,K] @ B[K,N] + bias[N]
// R13 memory layout (coalesced B along N, conflict-free scalar-LDS frags),
// inputs pre-rounded to tf32, cp.async double-buffered global->smem.
// 128 threads / 4 warps, block 128x128, warp tile 64x64, BK=16.
// ---------------------------------------------------------------------------
__global__ __launch_bounds__(128) void gemm_tf32(
    const float* __restrict__ A, const float* __restrict__ B,
    const float* __restrict__ bias, float* __restrict__ C,
    int M, int N, int K, int roundOut)
{
    __shared__ float As[2][128 * AST];
    __shared__ float Bs[2][16 * BST];

    int tid  = threadIdx.x;
    int w    = tid >> 5, lane = tid & 31;
    int g    = lane >> 2, t = lane & 3;
    int wm   = w >> 1,  wn = w & 1;
    int bx = blockIdx.x, by = blockIdx.y;

    const float* A0 = A + (size_t)by * 128 * K;
    const float* B0 = B + (size_t)bx * 128;

    int aRow = tid >> 2;          // 0..31 (rows aRow + i*32)
    int aCol = (tid & 3) * 4;     // 0,4,8,12
    int bRow = w;                 // 0..3  (rows bRow + i*4)
    int bCol = lane * 4;          // 0..124

    uint32_t sA0 = (uint32_t)__cvta_generic_to_shared(&As[0][0]);
    uint32_t sB0 = (uint32_t)__cvta_generic_to_shared(&Bs[0][0]);
    const uint32_t ABYTES = 128 * AST * 4;
    const uint32_t BBYTES = 16 * BST * 4;

    float acc[4][8][4];
    #pragma unroll
    for (int mt = 0; mt < 4; mt++)
        #pragma unroll
        for (int nt = 0; nt < 8; nt++)
            #pragma unroll
            for (int i = 0; i < 4; i++) acc[mt][nt][i] = 0.f;

    // prologue: fill buffer 0 (k0 = 0)
    #pragma unroll
    for (int i = 0; i < 4; i++) {
        int r = aRow + i * 32;
        cp16(sA0 + (uint32_t)(r * AST + aCol) * 4, A0 + (size_t)r * K + aCol);
    }
    #pragma unroll
    for (int i = 0; i < 4; i++) {
        int r = bRow + i * 4;
        cp16(sB0 + (uint32_t)(r * BST + bCol) * 4, B0 + (size_t)r * N + bCol);
    }
    asm volatile("cp.async.commit_group;");

    for (int k0 = 0; k0 < K; k0 += 16) {
        int p = (k0 >> 4) & 1;
        asm volatile("cp.async.wait_group 0;" ::: "memory");
        __syncthreads();

        // prefetch next k-tile into the other buffer (overlaps with MMAs)
        if (k0 + 16 < K) {
            uint32_t pa = (p ^ 1) * ABYTES;
            uint32_t pbb = (p ^ 1) * BBYTES;
            #pragma unroll
            for (int i = 0; i < 4; i++) {
                int r = aRow + i * 32;
                cp16(sA0 + pa + (uint32_t)(r * AST + aCol) * 4,
                     A0 + (size_t)r * K + k0 + 16 + aCol);
            }
            #pragma unroll
            for (int i = 0; i < 4; i++) {
                int r = bRow + i * 4;
                cp16(sB0 + pbb + (uint32_t)(r * BST + bCol) * 4,
                     B0 + (size_t)(k0 + 16 + r) * N + bCol);
            }
            asm volatile("cp.async.commit_group;");
        }

        #pragma unroll
        for (int kk = 0; kk < 16; kk += 8) {
            float af[4][4];
            #pragma unroll
            for (int mt = 0; mt < 4; mt++) {
                int m = wm * 64 + mt * 16 + g;
                af[mt][0] = As[p][m * AST + kk + t];
                af[mt][1] = As[p][(m + 8) * AST + kk + t];
                af[mt][2] = As[p][m * AST + kk + t + 4];
                af[mt][3] = As[p][(m + 8) * AST + kk + t + 4];
            }
            float bf[8][2];
            #pragma unroll
            for (int nt = 0; nt < 8; nt++) {
                int n = wn * 64 + nt * 8 + g;
                bf[nt][0] = Bs[p][(kk + t) * BST + n];
                bf[nt][1] = Bs[p][(kk + t + 4) * BST + n];
            }
            #pragma unroll
            for (int mt = 0; mt < 4; mt++)
                #pragma unroll
                for (int nt = 0; nt < 8; nt++)
                    mma_tf32(acc[mt][nt], af[mt], bf[nt]);
        }
    }

    #pragma unroll
    for (int mt = 0; mt < 4; mt++) {
        #pragma unroll
        for (int nt = 0; nt < 8; nt++) {
            int r0 = by * 128 + wm * 64 + mt * 16 + g;
            int c0 = bx * 128 + wn * 64 + nt * 8 + 2 * t;
            float b0 = bias[c0], b1 = bias[c0 + 1];
            float v0 = acc[mt][nt][0] + b0, v1 = acc[mt][nt][1] + b1;
            float v2 = acc[mt][nt][2] + b0, v3 = acc[mt][nt][3] + b1;
            if (roundOut) {
                v0 = f2tf(v0); v1 = f2tf(v1); v2 = f2tf(v2); v3 = f2tf(v3);
            }
            *(float2*)(C + (size_t)r0 * N + c0)       = make_float2(v0, v1);
            *(float2*)(C + (size_t)(r0 + 8) * N + c0) = make_float2(v2, v3);
        }
    }
}

// ---------------------------------------------------------------------------
// Two-pass tensor-core flash attention, post-softmax threshold, no max
// subtraction. qkv arrives pre-rounded to tf32 (GEMM epilogue), so K/V/Q
// commits are plain copies. y is tf32-rounded at write for the proj GEMM.
// ---------------------------------------------------------------------------
__global__ __launch_bounds__(256) void attn_tf32(
    const float* __restrict__ qkv, float* __restrict__ y)
{
    extern __shared__ float sm[];
    float* K0   = sm;                    // [64][KS] (also Q staging / osum)
    float* K1   = K0 + 64 * KS;
    float* V0   = K1 + 64 * KS;          // [64][VS]
    float* V1   = V0 + 64 * VS;
    float* red  = V1 + 64 * VS;          // [128]
    float* zinv = red + 128;             // [64]
    float* osum = K0;                    // [4][32][OST] overlay after pass 2

    int tid = threadIdx.x;
    int w = tid >> 5, lane = tid & 31;
    int g = lane >> 2, t = lane & 3;
    int wm = w >> 1, wn = w & 1;
    int qt = blockIdx.x, h = blockIdx.y, b = blockIdx.z;

    const float* Qg = qkv + ((size_t)(b * T_SEQ + qt * 64)) * C3 + h * HD;
    const float* Kg = qkv + (size_t)b * T_SEQ * C3 + CDIM + h * HD;
    const float* Vg = Kg + CDIM;

    int lr = tid >> 2;
    int lc = (tid & 3) * 4;

    // stage Q (scaled by exact 1/8; input already tf32) and hoist fragments
    #pragma unroll
    for (int cc = 0; cc < 4; cc++) {
        float4 v = *(const float4*)(Qg + (size_t)lr * C3 + lc + cc * 16);
        *(float4*)&K0[lr * KS + lc + cc * 16] =
            make_float4(v.x * 0.125f, v.y * 0.125f, v.z * 0.125f, v.w * 0.125f);
    }
    __syncthreads();

    int r1 = wm * 16 + g, r2 = r1 + 8;

    float qa[8][4];
    #pragma unroll
    for (int kc = 0; kc < 8; kc++) {
        qa[kc][0] = K0[r1 * KS + kc * 8 + t];
        qa[kc][1] = K0[r2 * KS + kc * 8 + t];
        qa[kc][2] = K0[r1 * KS + kc * 8 + t + 4];
        qa[kc][3] = K0[r2 * KS + kc * 8 + t + 4];
    }
    __syncthreads();

    // ================= Pass 1: Z only, registers =================
    float z1 = 0.f, z2 = 0.f;
    float4 rk[4];
    #pragma unroll
    for (int cc = 0; cc < 4; cc++)
        rk[cc] = *(const float4*)(Kg + (size_t)lr * C3 + lc + cc * 16);

    for (int kt = 0; kt < 16; kt++) {
        float* Kb = (kt & 1) ? K1 : K0;
        #pragma unroll
        for (int cc = 0; cc < 4; cc++)
            *(float4*)&Kb[lr * KS + lc + cc * 16] = rk[cc];
        __syncthreads();

        if (kt < 15) {
            #pragma unroll
            for (int cc = 0; cc < 4; cc++)
                rk[cc] = *(const float4*)(Kg + (size_t)((kt + 1) * 64 + lr) * C3 + lc + cc * 16);
        }

        float s[4][4];
        #pragma unroll
        for (int nt = 0; nt < 4; nt++)
            #pragma unroll
            for (int i = 0; i < 4; i++) s[nt][i] = 0.f;

        #pragma unroll
        for (int kc = 0; kc < 8; kc++) {
            float bf[4][2];
            #pragma unroll
            for (int nt = 0; nt < 4; nt++) {
                int kr = wn * 32 + nt * 8 + g;
                bf[nt][0] = Kb[kr * KS + kc * 8 + t];
                bf[nt][1] = Kb[kr * KS + kc * 8 + t + 4];
            }
            #pragma unroll
            for (int nt = 0; nt < 4; nt++) mma_tf32(s[nt], qa[kc], bf[nt]);
        }

        #pragma unroll
        for (int nt = 0; nt < 4; nt++) {
            z1 += __expf(s[nt][0]) + __expf(s[nt][1]);
            z2 += __expf(s[nt][2]) + __expf(s[nt][3]);
        }
    }

    z1 += __shfl_xor_sync(0xffffffffu, z1, 1);
    z1 += __shfl_xor_sync(0xffffffffu, z1, 2);
    z2 += __shfl_xor_sync(0xffffffffu, z2, 1);
    z2 += __shfl_xor_sync(0xffffffffu, z2, 2);
    if (t == 0) { red[wn * 64 + r1] = z1; red[wn * 64 + r2] = z2; }
    __syncthreads();
    if (tid < 64) zinv[tid] = 1.f / (red[tid] + red[64 + tid]);
    __syncthreads();
    float li1 = zinv[r1], li2 = zinv[r2];

    float o[8][4];
    #pragma unroll
    for (int nt = 0; nt < 8; nt++)
        #pragma unroll
        for (int i = 0; i < 4; i++) o[nt][i] = 0.f;

    // ================= Pass 2: threshold + PV (shfl fragments) =============
    float4 rv[4];
    #pragma unroll
    for (int cc = 0; cc < 4; cc++) {
        rk[cc] = *(const float4*)(Kg + (size_t)lr * C3 + lc + cc * 16);
        rv[cc] = *(const float4*)(Vg + (size_t)lr * C3 + lc + cc * 16);
    }

    int srcA = (lane & 28) | (t >> 1);
    int srcB = srcA + 2;

    for (int kt = 0; kt < 16; kt++) {
        float* Kb = (kt & 1) ? K1 : K0;
        float* Vb = (kt & 1) ? V1 : V0;
        #pragma unroll
        for (int cc = 0; cc < 4; cc++) {
            *(float4*)&Kb[lr * KS + lc + cc * 16] = rk[cc];
            *(float4*)&Vb[lr * VS + lc + cc * 16] = rv[cc];
        }
        __syncthreads();

        if (kt < 15) {
            #pragma unroll
            for (int cc = 0; cc < 4; cc++) {
                size_t rg = (size_t)((kt + 1) * 64 + lr) * C3 + lc + cc * 16;
                rk[cc] = *(const float4*)(Kg + rg);
                rv[cc] = *(const float4*)(Vg + rg);
            }
        }

        float s[4][4];
        #pragma unroll
        for (int nt = 0; nt < 4; nt++)
            #pragma unroll
            for (int i = 0; i < 4; i++) s[nt][i] = 0.f;

        #pragma unroll
        for (int kc = 0; kc < 8; kc++) {
            float bf[4][2];
            #pragma unroll
            for (int nt = 0; nt < 4; nt++) {
                int kr = wn * 32 + nt * 8 + g;
                bf[nt][0] = Kb[kr * KS + kc * 8 + t];
                bf[nt][1] = Kb[kr * KS + kc * 8 + t + 4];
            }
            #pragma unroll
            for (int nt = 0; nt < 4; nt++) mma_tf32(s[nt], qa[kc], bf[nt]);
        }

        #pragma unroll
        for (int nt = 0; nt < 4; nt++) {
            s[nt][0] = f2tf(fmaxf(__expf(s[nt][0]) * li1 - THRESH, 0.f));
            s[nt][1] = f2tf(fmaxf(__expf(s[nt][1]) * li1 - THRESH, 0.f));
            s[nt][2] = f2tf(fmaxf(__expf(s[nt][2]) * li2 - THRESH, 0.f));
            s[nt][3] = f2tf(fmaxf(__expf(s[nt][3]) * li2 - THRESH, 0.f));
        }

        bool odd = (t & 1);
        #pragma unroll
        for (int kc = 0; kc < 4; kc++) {
            float e0 = __shfl_sync(0xffffffffu, s[kc][0], srcA);
            float e1 = __shfl_sync(0xffffffffu, s[kc][1], srcA);
            float e2 = __shfl_sync(0xffffffffu, s[kc][2], srcA);
            float e3 = __shfl_sync(0xffffffffu, s[kc][3], srcA);
            float f0 = __shfl_sync(0xffffffffu, s[kc][0], srcB);
            float f1 = __shfl_sync(0xffffffffu, s[kc][1], srcB);
            float f2 = __shfl_sync(0xffffffffu, s[kc][2], srcB);
            float f3 = __shfl_sync(0xffffffffu, s[kc][3], srcB);
            float pa[4];
            pa[0] = odd ? e1 : e0;
            pa[1] = odd ? e3 : e2;
            pa[2] = odd ? f1 : f0;
            pa[3] = odd ? f3 : f2;

            int krow = wn * 32 + kc * 8;
            #pragma unroll
            for (int nt = 0; nt < 8; nt++) {
                int dc = nt * 8 + g;
                float bf[2];
                bf[0] = Vb[(krow + t) * VS + dc];
                bf[1] = Vb[(krow + t + 4) * VS + dc];
                mma_tf32(o[nt], pa, bf);
            }
        }
    }

    // reduce O across the two key-halves, write y tf32-rounded (proj A input)
    __syncthreads();
    if (wn == 1) {
        float* dst = osum + (wm * 32 + lane) * OST;
        #pragma unroll
        for (int nt = 0; nt < 8; nt++)
            *(float4*)(dst + nt * 4) = *(float4*)o[nt];
    }
    __syncthreads();
    if (wn == 0) {
        const float* src = osum + (wm * 32 + lane) * OST;
        size_t rowg = (size_t)b * T_SEQ + qt * 64;
        #pragma unroll
        for (int nt = 0; nt < 8; nt++) {
            float4 p = *(const float4*)(src + nt * 4);
            int c0 = h * HD + nt * 8 + 2 * t;
            *(float2*)(y + (rowg + r1) * CDIM + c0) =
                make_float2(f2tf(o[nt][0] + p.x), f2tf(o[nt][1] + p.y));
            *(float2*)(y + (rowg + r2) * CDIM + c0) =
                make_float2(f2tf(o[nt][2] + p.z), f2tf(o[nt][3] + p.w));
        }
    }
}

// ---------------------------------------------------------------------------

extern "C" void kernel_launch(void* const* d_in, const int* in_sizes, int n_in,
                              void* d_out, int out_size)
{
    const float* x      = (const float*)d_in[0];
    const float* w_attn = (const float*)d_in[1];
    const float* b_attn = (const float*)d_in[2];
    const float* w_proj = (const float*)d_in[3];
    const float* b_proj = (const float*)d_in[4];
    float* out = (float*)d_out;

    float *qkv, *yb, *xr, *war, *wpr;
    cudaGetSymbolAddress((void**)&qkv, g_qkv);
    cudaGetSymbolAddress((void**)&yb,  g_y);
    cudaGetSymbolAddress((void**)&xr,  g_xr);
    cudaGetSymbolAddress((void**)&war, g_war);
    cudaGetSymbolAddress((void**)&wpr, g_wpr);

    const int SMEM_ATTN =
        (2 * 64 * KS + 2 * 64 * VS + 128 + 64) * (int)sizeof(float);
    cudaFuncSetAttribute(attn_tf32,
                         cudaFuncAttributeMaxDynamicSharedMemorySize, SMEM_ATTN);

    // 0) prepasses: tf32-round x and weights (layouts unchanged -> coalesced GEMM)
    int nx = (BATCH * T_SEQ * CDIM) / 4;
    round_tf32<<<(nx + 255) / 256, 256>>>((const float4*)x, (float4*)xr, nx);
    int nwa = (CDIM * C3) / 4;
    round_tf32<<<(nwa + 255) / 256, 256>>>((const float4*)w_attn, (float4*)war, nwa);
    int nwp = (CDIM * CDIM) / 4;
    round_tf32<<<(nwp + 255) / 256, 256>>>((const float4*)w_proj, (float4*)wpr, nwp);

    // 1) QKV = xr @ war + b_attn, output rounded to tf32
    gemm_tf32<<<dim3(C3 / 128, (BATCH * T_SEQ) / 128), 128>>>(
        xr, war, b_attn, qkv, BATCH * T_SEQ, C3, CDIM, 1);

    // 2) attention with post-softmax threshold -> y (tf32-rounded)
    attn_tf32<<<dim3(T_SEQ / 64, NH, BATCH), 256, SMEM_ATTN>>>(qkv, yb);

    // 3) out = y @ wpr + b_proj (fp32 output)
    gemm_tf32<<<dim3(CDIM / 128, (BATCH * T_SEQ) / 128), 128>>>(
        yb, wpr, b_proj, out, BATCH * T_SEQ, CDIM, CDIM, 0);
}